// round 3
// baseline (speedup 1.0000x reference)
#include <cuda_runtime.h>

// Problem constants (fixed by the reference)
#define VV   4096                 // vocab
#define MM   4                    // markov order
#define BB   8
#define LL   2048
#define FAN  (MM * (VV + 1))      // 16388
#define NPOS (BB * LL)            // 16384

// Scratch: transposed table Wt[fan_in][V], fully coalesced gather rows.
// 16388 * 4096 * 4 B = 268 MB static device array (allowed; no cudaMalloc).
__device__ float g_Wt[(size_t)FAN * VV];

// ---------------------------------------------------------------------------
// Kernel 1: W [V, FAN] row-major  ->  g_Wt [FAN, V] row-major.
// Classic 32x32 tile via padded shared memory; coalesced on both sides.
// grid = (ceil(FAN/32)=513, V/32=128), block = (32, 8).
// ---------------------------------------------------------------------------
__global__ void ngram_transpose_kernel(const float* __restrict__ W) {
    __shared__ float tile[32][33];

    const int c0 = blockIdx.x * 32;   // fan_in tile origin (needs bounds: 16388 % 32 != 0)
    const int v0 = blockIdx.y * 32;   // vocab tile origin (always in-bounds: 4096 % 32 == 0)
    const int tx = threadIdx.x;
    const int ty = threadIdx.y;

    const int c = c0 + tx;
    if (c < FAN) {
        #pragma unroll
        for (int j = 0; j < 32; j += 8) {
            // coalesced read along fan_in
            tile[ty + j][tx] = W[(size_t)(v0 + ty + j) * FAN + c];
        }
    }
    __syncthreads();

    const int v = v0 + tx;
    #pragma unroll
    for (int j = 0; j < 32; j += 8) {
        const int cc = c0 + ty + j;
        if (cc < FAN) {
            // coalesced write along vocab
            g_Wt[(size_t)cc * VV + v] = tile[tx][ty + j];
        }
    }
}

// ---------------------------------------------------------------------------
// Kernel 2: per-position gather-sum.
// One block per (b,l) position; 256 threads; each thread produces 4 float4
// (16 output floats). out[pos, v] = bias[v] + sum_k Wt[k*(V+1)+tok_k][v].
// Row pointers computed redundantly per thread (idx loads hit L1).
// ---------------------------------------------------------------------------
__global__ __launch_bounds__(256)
void ngram_gather_kernel(const int* __restrict__ idx,
                         const float* __restrict__ bias,
                         float* __restrict__ out) {
    const int pos = blockIdx.x;        // 0 .. NPOS-1
    const int b   = pos >> 11;         // / LL
    const int l   = pos & (LL - 1);    // % LL

    const float4* rows[MM];
    #pragma unroll
    for (int k = 0; k < MM; k++) {
        const int s   = MM - 1 - k;
        const int tok = (l >= s) ? idx[b * LL + (l - s)] : VV;   // pad token = V
        rows[k] = reinterpret_cast<const float4*>(
                      g_Wt + (size_t)(k * (VV + 1) + tok) * VV);
    }

    const float4* b4 = reinterpret_cast<const float4*>(bias);
    float4*       o4 = reinterpret_cast<float4*>(out + (size_t)pos * VV);

    // V/4 = 1024 float4 elements; 256 threads -> exactly 4 iterations.
    #pragma unroll
    for (int j = 0; j < (VV / 4) / 256; j++) {
        const int i = threadIdx.x + j * 256;
        float4 r  = b4[i];
        #pragma unroll
        for (int k = 0; k < MM; k++) {
            const float4 t = rows[k][i];
            r.x += t.x; r.y += t.y; r.z += t.z; r.w += t.w;
        }
        o4[i] = r;
    }
}

// ---------------------------------------------------------------------------
// Launch: identify inputs by element count (robust to metadata ordering):
//   idx  : B*L   = 16384 (int32)
//   W    : V*FAN = 67,125,248 (f32)
//   bias : V     = 4096 (f32)
// ---------------------------------------------------------------------------
extern "C" void kernel_launch(void* const* d_in, const int* in_sizes, int n_in,
                              void* d_out, int out_size) {
    const int*   idx  = nullptr;
    const float* W    = nullptr;
    const float* bias = nullptr;

    for (int i = 0; i < n_in; i++) {
        if (in_sizes[i] == NPOS)      idx  = (const int*)d_in[i];
        else if (in_sizes[i] == VV)   bias = (const float*)d_in[i];
        else                          W    = (const float*)d_in[i];
    }

    dim3 tblock(32, 8);
    dim3 tgrid((FAN + 31) / 32, VV / 32);
    ngram_transpose_kernel<<<tgrid, tblock>>>(W);

    ngram_gather_kernel<<<NPOS, 256>>>(idx, bias, (float*)d_out);
}

// round 4
// speedup vs baseline: 1.0886x; 1.0886x over previous
#include <cuda_runtime.h>

// Problem constants (fixed by the reference)
#define VV   4096                 // vocab
#define MM   4                    // markov order
#define BB   8
#define LL   2048
#define FAN  (MM * (VV + 1))      // 16388  (multiple of 4 -> float4-aligned)
#define NPOS (BB * LL)            // 16384

#define VC   512                  // vocab chunk (chunk working set = 33.5 MB << L2)
#define NCH  (VV / VC)            // 8 chunks
#define PPB  4                    // positions per gather block

// Scratch: transposed table Wt[fan_in][V]. 268 MB static device array.
// Table-0 rows (c < V+1) additionally carry the bias folded in.
__device__ float g_Wt[(size_t)FAN * VV];

// ---------------------------------------------------------------------------
// Kernel 1: W [V, FAN] row-major -> g_Wt [FAN, V] row-major, float4 both sides.
// Bias b[v] is folded into rows c < V+1 (table 0), so the gather skips it.
// grid = (ceil(FAN/32)=513, V/32=128), block = (8, 32).
// y (v-tiles) is the outer grid dim => last-executed blocks write high-v rows,
// which the gather consumes first (descending chunk order) while L2-warm.
// ---------------------------------------------------------------------------
__global__ __launch_bounds__(256)
void ngram_transpose_kernel(const float* __restrict__ W,
                            const float* __restrict__ bias) {
    __shared__ float tile[32][33];

    const int c0 = blockIdx.x * 32;   // fan_in tile origin
    const int v0 = blockIdx.y * 32;   // vocab tile origin (4096 % 32 == 0)
    const int tx = threadIdx.x;       // 0..7  (float4 quad)
    const int ty = threadIdx.y;       // 0..31

    // Read: coalesced float4 along fan_in. c is a multiple of 4; FAN % 4 == 0,
    // so a quad is valid iff its first element is in range.
    {
        const int c = c0 + tx * 4;
        if (c < FAN) {
            const float4 w = *reinterpret_cast<const float4*>(
                &W[(size_t)(v0 + ty) * FAN + c]);
            tile[ty][tx * 4 + 0] = w.x;
            tile[ty][tx * 4 + 1] = w.y;
            tile[ty][tx * 4 + 2] = w.z;
            tile[ty][tx * 4 + 3] = w.w;
        }
    }
    __syncthreads();

    // Write: coalesced float4 along vocab. Row cc = c0 + ty.
    {
        const int cc = c0 + ty;
        if (cc < FAN) {
            const int vq = v0 + tx * 4;
            float4 o;
            o.x = tile[tx * 4 + 0][ty];
            o.y = tile[tx * 4 + 1][ty];
            o.z = tile[tx * 4 + 2][ty];
            o.w = tile[tx * 4 + 3][ty];
            if (cc < VV + 1) {                 // table 0: fold bias in
                const float4 bb = *reinterpret_cast<const float4*>(&bias[vq]);
                o.x += bb.x; o.y += bb.y; o.z += bb.z; o.w += bb.w;
            }
            *reinterpret_cast<float4*>(&g_Wt[(size_t)cc * VV + vq]) = o;
        }
    }
}

// ---------------------------------------------------------------------------
// Kernel 2: chunked gather-sum.
// grid = (NPOS/PPB = 4096, NCH = 8), block = 256.
// blockIdx.y selects the vocab chunk (processed descending so the transpose's
// freshest L2 lines are consumed first). Blocks dispatch in linear bid order,
// so one chunk's 33.5 MB slice of g_Wt stays L2-resident while all 16384
// positions sweep it; gather DRAM reads collapse to ~one touch per line.
// Output stores are streaming (__stcs) to avoid evicting the chunk.
// ---------------------------------------------------------------------------
__global__ __launch_bounds__(256)
void ngram_gather_kernel(const int* __restrict__ idx,
                         float* __restrict__ out) {
    const int chunk = (NCH - 1) - blockIdx.y;   // descending chunk order
    const int v0    = chunk * VC;
    const int p0    = blockIdx.x * PPB;

    __shared__ const float4* rows[PPB][MM];

    const int t = threadIdx.x;
    if (t < PPB * MM) {
        const int pl  = t >> 2;
        const int k   = t & 3;
        const int pos = p0 + pl;
        const int b   = pos >> 11;          // / LL
        const int l   = pos & (LL - 1);     // % LL
        const int s   = MM - 1 - k;
        const int tok = (l >= s) ? idx[b * LL + (l - s)] : VV;  // pad token = V
        rows[pl][k] = reinterpret_cast<const float4*>(
            g_Wt + (size_t)(k * (VV + 1) + tok) * VV + v0);
    }
    __syncthreads();

    // PPB * (VC/4) = 4 * 128 = 512 float4 items; 256 threads -> 2 iterations.
    #pragma unroll
    for (int it = 0; it < (PPB * (VC / 4)) / 256; it++) {
        const int item = t + it * 256;
        const int pl   = item >> 7;         // / (VC/4)
        const int i    = item & (VC / 4 - 1);

        const float4 a0 = rows[pl][0][i];   // carries the bias
        const float4 a1 = rows[pl][1][i];
        const float4 a2 = rows[pl][2][i];
        const float4 a3 = rows[pl][3][i];

        float4 r;
        r.x = (a0.x + a1.x) + (a2.x + a3.x);
        r.y = (a0.y + a1.y) + (a2.y + a3.y);
        r.z = (a0.z + a1.z) + (a2.z + a3.z);
        r.w = (a0.w + a1.w) + (a2.w + a3.w);

        float4* o4 = reinterpret_cast<float4*>(
            out + (size_t)(p0 + pl) * VV + v0) + i;
        __stcs(o4, r);                      // streaming store: don't pollute L2
    }
}

// ---------------------------------------------------------------------------
// Launch. Inputs identified by element count:
//   idx : B*L = 16384 (int32), bias : V = 4096, W : V*FAN (largest)
// ---------------------------------------------------------------------------
extern "C" void kernel_launch(void* const* d_in, const int* in_sizes, int n_in,
                              void* d_out, int out_size) {
    const int*   idx  = nullptr;
    const float* W    = nullptr;
    const float* bias = nullptr;

    for (int i = 0; i < n_in; i++) {
        if (in_sizes[i] == NPOS)      idx  = (const int*)d_in[i];
        else if (in_sizes[i] == VV)   bias = (const float*)d_in[i];
        else                          W    = (const float*)d_in[i];
    }

    dim3 tblock(8, 32);
    dim3 tgrid((FAN + 31) / 32, VV / 32);   // y (v-tiles) outer
    ngram_transpose_kernel<<<tgrid, tblock>>>(W, bias);

    dim3 ggrid(NPOS / PPB, NCH);
    ngram_gather_kernel<<<ggrid, 256>>>(idx, (float*)d_out);
}

// round 7
// speedup vs baseline: 1.4600x; 1.3412x over previous
#include <cuda_runtime.h>

// Problem constants (fixed by the reference)
#define VV   4096                 // vocab
#define MM   4                    // markov order
#define BB   8
#define LL   2048
#define FAN  (MM * (VV + 1))      // 16388  (multiple of 4 -> float4-aligned rows)
#define NPOS (BB * LL)            // 16384

#define VC   512                  // vocab chunk (slab = 33.5 MB << 126 MB L2)
#define NCH  (VV / VC)            // 8 chunks

#define NSUB 4                    // subtiles per transpose block (along fan_in)
#define CT   (NSUB * 32)          // 128 fan_in columns per block
#define CMAIN 16384               // fan_in covered by main transpose (divides CT)

// Scratch: transposed table Wt[fan_in][V]. 268 MB static device array.
// Table-0 rows (c < V+1) carry the bias folded in.
__device__ float g_Wt[(size_t)FAN * VV];

// ---------------------------------------------------------------------------
// Kernel 1a: main transpose, W [V, FAN] -> g_Wt [FAN, V].
// Block (8,32) = 256 threads processes a 32v x 128c region as 4 independent
// 32x32 subtiles, each using the proven 32x33 scalar-smem layout
// (conflict-free on both phases; all float4 accesses are GLOBAL only and
// 16B-aligned by construction). Each thread: 4 independent LDG.128 then
// 4 independent STG.128 (MLP=4).
// grid = (CMAIN/CT = 128, V/32 = 128); y (v-tiles) outer so last-written
// lines are high-v, which the gather consumes first (descending chunks).
// ---------------------------------------------------------------------------
__global__ __launch_bounds__(256)
void ngram_transpose_main(const float* __restrict__ W,
                          const float* __restrict__ bias) {
    __shared__ float tile[NSUB][32][33];

    const int c0 = blockIdx.x * CT;   // fan_in origin
    const int v0 = blockIdx.y * 32;   // vocab origin (4096 % 32 == 0)
    const int tx = threadIdx.x;       // 0..7
    const int ty = threadIdx.y;       // 0..31

    // Load phase: 4 independent float4 global reads, scalar smem writes.
    float4 w4[NSUB];
    const float* wrow = &W[(size_t)(v0 + ty) * FAN + c0 + tx * 4];
    #pragma unroll
    for (int s = 0; s < NSUB; s++)
        w4[s] = *reinterpret_cast<const float4*>(wrow + s * 32);
    #pragma unroll
    for (int s = 0; s < NSUB; s++) {
        tile[s][ty][tx * 4 + 0] = w4[s].x;
        tile[s][ty][tx * 4 + 1] = w4[s].y;
        tile[s][ty][tx * 4 + 2] = w4[s].z;
        tile[s][ty][tx * 4 + 3] = w4[s].w;
    }
    __syncthreads();

    // Store phase: scalar smem reads, 4 independent float4 global writes.
    // Thread -> vocab quad v0 + tx*4, fan row cc = c0 + s*32 + ty.
    const bool foldblk = (c0 < VV + 1);
    float4 bb = make_float4(0.f, 0.f, 0.f, 0.f);
    if (foldblk) bb = *reinterpret_cast<const float4*>(&bias[v0 + tx * 4]);

    #pragma unroll
    for (int s = 0; s < NSUB; s++) {
        const int cc = c0 + s * 32 + ty;
        float4 o;
        o.x = tile[s][tx * 4 + 0][ty];
        o.y = tile[s][tx * 4 + 1][ty];
        o.z = tile[s][tx * 4 + 2][ty];
        o.w = tile[s][tx * 4 + 3][ty];
        if (foldblk && cc < VV + 1) {        // table 0: fold bias in
            o.x += bb.x; o.y += bb.y; o.z += bb.z; o.w += bb.w;
        }
        *reinterpret_cast<float4*>(&g_Wt[(size_t)cc * VV + v0 + tx * 4]) = o;
    }
}

// ---------------------------------------------------------------------------
// Kernel 1b: remainder rows cc = 16384..16387 (table-3 tokens 4093..4095 and
// the table-3 pad row). 4 rows x 4096 = 16384 elements -> grid MUST be 64
// blocks of 256 (16 blocks only covered row 16384 and caused R5's 1.16e-2
// rel_err). Strided scalar reads (64 KB logical), coalesced scalar writes.
// ---------------------------------------------------------------------------
__global__ __launch_bounds__(256)
void ngram_transpose_rem(const float* __restrict__ W) {
    const int e = blockIdx.x * 256 + threadIdx.x;   // 0..16383
    const int r = e >> 12;                          // 0..3
    const int v = e & (VV - 1);
    g_Wt[(size_t)(CMAIN + r) * VV + v] = W[(size_t)v * FAN + CMAIN + r];
}

// ---------------------------------------------------------------------------
// Kernel 2: chunked gather-sum, warp-per-position.
// grid = (NPOS/8 = 2048, NCH = 8), block = 256 (8 warps = 8 positions).
// Row pointers live in registers (no LDS in the hot loop); inner loop is
// 4 fully-unrolled iterations of 4 independent LDG.128 -> ~16 loads in
// flight per thread. Chunks processed descending (consume transpose's
// freshest L2 lines first); streaming stores keep the chunk L2-resident.
// All gather addresses are multiples of 16 B.
// ---------------------------------------------------------------------------
__global__ __launch_bounds__(256, 4)
void ngram_gather_kernel(const int* __restrict__ idx,
                         float* __restrict__ out) {
    const int chunk = (NCH - 1) - blockIdx.y;
    const int v0    = chunk * VC;
    const int warp  = threadIdx.x >> 5;
    const int lane  = threadIdx.x & 31;

    const int pos = blockIdx.x * 8 + warp;
    const int b   = pos >> 11;           // / LL
    const int l   = pos & (LL - 1);      // % LL

    const float4* r0; const float4* r1; const float4* r2; const float4* r3;
    {
        int tok;
        tok = (l >= 3) ? __ldg(&idx[b * LL + l - 3]) : VV;
        r0 = reinterpret_cast<const float4*>(g_Wt + (size_t)(0 * (VV + 1) + tok) * VV + v0);
        tok = (l >= 2) ? __ldg(&idx[b * LL + l - 2]) : VV;
        r1 = reinterpret_cast<const float4*>(g_Wt + (size_t)(1 * (VV + 1) + tok) * VV + v0);
        tok = (l >= 1) ? __ldg(&idx[b * LL + l - 1]) : VV;
        r2 = reinterpret_cast<const float4*>(g_Wt + (size_t)(2 * (VV + 1) + tok) * VV + v0);
        tok = __ldg(&idx[b * LL + l]);
        r3 = reinterpret_cast<const float4*>(g_Wt + (size_t)(3 * (VV + 1) + tok) * VV + v0);
    }

    float4* o4 = reinterpret_cast<float4*>(out + (size_t)pos * VV + v0);

    // VC/4 = 128 float4 / 32 lanes = 4 iterations.
    #pragma unroll
    for (int i = 0; i < VC / 4 / 32; i++) {
        const int j = lane + i * 32;
        const float4 a0 = r0[j];     // r0 carries the folded bias
        const float4 a1 = r1[j];
        const float4 a2 = r2[j];
        const float4 a3 = r3[j];
        float4 r;
        r.x = (a0.x + a1.x) + (a2.x + a3.x);
        r.y = (a0.y + a1.y) + (a2.y + a3.y);
        r.z = (a0.z + a1.z) + (a2.z + a3.z);
        r.w = (a0.w + a1.w) + (a2.w + a3.w);
        __stcs(&o4[j], r);           // streaming store: don't evict the chunk
    }
}

// ---------------------------------------------------------------------------
// Launch. Inputs identified by element count:
//   idx : B*L = 16384 (int32), bias : V = 4096, W : V*FAN (largest)
// ---------------------------------------------------------------------------
extern "C" void kernel_launch(void* const* d_in, const int* in_sizes, int n_in,
                              void* d_out, int out_size) {
    const int*   idx  = nullptr;
    const float* W    = nullptr;
    const float* bias = nullptr;

    for (int i = 0; i < n_in; i++) {
        if (in_sizes[i] == NPOS)      idx  = (const int*)d_in[i];
        else if (in_sizes[i] == VV)   bias = (const float*)d_in[i];
        else                          W    = (const float*)d_in[i];
    }

    dim3 tblock(8, 32);
    dim3 tgrid(CMAIN / CT, VV / 32);          // (128, 128), y outer
    ngram_transpose_main<<<tgrid, tblock>>>(W, bias);
    ngram_transpose_rem<<<64, 256>>>(W);      // 64*256 = 16384 = 4 rows * V

    dim3 ggrid(NPOS / 8, NCH);                // (2048, 8)
    ngram_gather_kernel<<<ggrid, 256>>>(idx, (float*)d_out);
}

// round 8
// speedup vs baseline: 1.7517x; 1.1998x over previous
#include <cuda_runtime.h>
#include <cuda_fp16.h>

// Problem constants (fixed by the reference)
#define VV   4096                 // vocab
#define MM   4                    // markov order
#define BB   8
#define LL   2048
#define FAN  (MM * (VV + 1))      // 16388
#define NPOS (BB * LL)            // 16384

#define VC   1024                 // vocab chunk (fp16 slab = 33.5 MB << 126 MB L2)
#define NCH  (VV / VC)            // 4 chunks

#define NSUB 4                    // subtiles per transpose block (along fan_in)
#define CT   (NSUB * 32)          // 128 fan_in columns per block
#define CMAIN 16384               // fan_in covered by main transpose

// Scratch: transposed table in fp16. 16388 * 4096 * 2 B = 134 MB.
// Precision: |W| <= 2^-7 -> fp16 rnd error <= 2^-18 abs; rel_err of the
// 4-term sum ~1.3e-4 << 1e-3. Bias is NOT folded (kept exact in fp32).
__device__ __half g_Wth[(size_t)FAN * VV];

// ---------------------------------------------------------------------------
// Kernel 1a: main transpose, W [V, FAN] fp32 -> g_Wth [FAN, V] fp16.
// Proven 4x 32x33 scalar-smem subtile scheme (conflict-free both phases).
// Per thread: 4 independent LDG.128, then per subtile 4 LDS + 2 cvt + STG.64.
// grid = (128, 128) with y (v-tiles) outer: last-written lines are high-v,
// consumed first by the gather (descending chunk order).
// ---------------------------------------------------------------------------
__global__ __launch_bounds__(256)
void ngram_transpose_main(const float* __restrict__ W) {
    __shared__ float tile[NSUB][32][33];

    const int c0 = blockIdx.x * CT;   // fan_in origin
    const int v0 = blockIdx.y * 32;   // vocab origin
    const int tx = threadIdx.x;       // 0..7
    const int ty = threadIdx.y;       // 0..31

    // Load phase: 4 independent float4 global reads, scalar smem writes.
    float4 w4[NSUB];
    const float* wrow = &W[(size_t)(v0 + ty) * FAN + c0 + tx * 4];
    #pragma unroll
    for (int s = 0; s < NSUB; s++)
        w4[s] = *reinterpret_cast<const float4*>(wrow + s * 32);
    #pragma unroll
    for (int s = 0; s < NSUB; s++) {
        tile[s][ty][tx * 4 + 0] = w4[s].x;
        tile[s][ty][tx * 4 + 1] = w4[s].y;
        tile[s][ty][tx * 4 + 2] = w4[s].z;
        tile[s][ty][tx * 4 + 3] = w4[s].w;
    }
    __syncthreads();

    // Store phase: scalar smem reads, convert to fp16, 8-byte global writes.
    // Thread -> vocab quad v0 + tx*4 (byte offset multiple of 8: aligned).
    #pragma unroll
    for (int s = 0; s < NSUB; s++) {
        const int cc = c0 + s * 32 + ty;
        const float x0 = tile[s][tx * 4 + 0][ty];
        const float x1 = tile[s][tx * 4 + 1][ty];
        const float x2 = tile[s][tx * 4 + 2][ty];
        const float x3 = tile[s][tx * 4 + 3][ty];
        const __half2 p0 = __floats2half2_rn(x0, x1);
        const __half2 p1 = __floats2half2_rn(x2, x3);
        uint2 o;
        o.x = *reinterpret_cast<const unsigned int*>(&p0);
        o.y = *reinterpret_cast<const unsigned int*>(&p1);
        *reinterpret_cast<uint2*>(&g_Wth[(size_t)cc * VV + v0 + tx * 4]) = o;
    }
}

// ---------------------------------------------------------------------------
// Kernel 1b: remainder rows cc = 16384..16387 (table-3 tokens 4093..4095 and
// the never-read table-3 pad row). 4 rows x 4096 = 16384 elements, grid 64.
// ---------------------------------------------------------------------------
__global__ __launch_bounds__(256)
void ngram_transpose_rem(const float* __restrict__ W) {
    const int e = blockIdx.x * 256 + threadIdx.x;   // 0..16383
    const int r = e >> 12;                          // 0..3
    const int v = e & (VV - 1);
    g_Wth[(size_t)(CMAIN + r) * VV + v] =
        __float2half_rn(W[(size_t)v * FAN + CMAIN + r]);
}

// ---------------------------------------------------------------------------
// Kernel 2: chunked fp16 gather-sum, warp-per-position.
// grid = (NPOS/8 = 2048, NCH = 4), block = 256 (8 warps = 8 positions).
// Row pointers in registers; inner loop = 4 iterations of 4 independent
// LDG.128 (8 halves each) + 2 bias LDG.128 (L2-hit) + cvt + 2 STG.128.
// Chunks descending; streaming stores keep the slab L2-resident.
// ---------------------------------------------------------------------------
__global__ __launch_bounds__(256, 4)
void ngram_gather_kernel(const int* __restrict__ idx,
                         const float* __restrict__ bias,
                         float* __restrict__ out) {
    const int chunk = (NCH - 1) - blockIdx.y;
    const int v0    = chunk * VC;
    const int warp  = threadIdx.x >> 5;
    const int lane  = threadIdx.x & 31;

    const int pos = blockIdx.x * 8 + warp;
    const int b   = pos >> 11;           // / LL
    const int l   = pos & (LL - 1);      // % LL

    const uint4* r0; const uint4* r1; const uint4* r2; const uint4* r3;
    {
        int tok;
        tok = (l >= 3) ? __ldg(&idx[b * LL + l - 3]) : VV;
        r0 = reinterpret_cast<const uint4*>(g_Wth + (size_t)(0 * (VV + 1) + tok) * VV + v0);
        tok = (l >= 2) ? __ldg(&idx[b * LL + l - 2]) : VV;
        r1 = reinterpret_cast<const uint4*>(g_Wth + (size_t)(1 * (VV + 1) + tok) * VV + v0);
        tok = (l >= 1) ? __ldg(&idx[b * LL + l - 1]) : VV;
        r2 = reinterpret_cast<const uint4*>(g_Wth + (size_t)(2 * (VV + 1) + tok) * VV + v0);
        tok = __ldg(&idx[b * LL + l]);
        r3 = reinterpret_cast<const uint4*>(g_Wth + (size_t)(3 * (VV + 1) + tok) * VV + v0);
    }

    const float4* b4 = reinterpret_cast<const float4*>(bias + v0);
    float4*       o4 = reinterpret_cast<float4*>(out + (size_t)pos * VV + v0);

    // VC/8 = 128 uint4 items per row / 32 lanes = 4 iterations.
    #pragma unroll
    for (int i = 0; i < VC / 8 / 32; i++) {
        const int j = lane + i * 32;

        const uint4 h0 = r0[j];
        const uint4 h1 = r1[j];
        const uint4 h2 = r2[j];
        const uint4 h3 = r3[j];
        const float4 ba = b4[2 * j];
        const float4 bb = b4[2 * j + 1];

        float acc[8] = {ba.x, ba.y, ba.z, ba.w, bb.x, bb.y, bb.z, bb.w};

        const uint4 hs[4] = {h0, h1, h2, h3};
        #pragma unroll
        for (int k = 0; k < 4; k++) {
            const __half2* hp = reinterpret_cast<const __half2*>(&hs[k]);
            #pragma unroll
            for (int q = 0; q < 4; q++) {
                const float2 t = __half22float2(hp[q]);
                acc[2 * q + 0] += t.x;
                acc[2 * q + 1] += t.y;
            }
        }

        float4 oA, oB;
        oA.x = acc[0]; oA.y = acc[1]; oA.z = acc[2]; oA.w = acc[3];
        oB.x = acc[4]; oB.y = acc[5]; oB.z = acc[6]; oB.w = acc[7];
        __stcs(&o4[2 * j],     oA);
        __stcs(&o4[2 * j + 1], oB);
    }
}

// ---------------------------------------------------------------------------
// Launch. Inputs identified by element count:
//   idx : B*L = 16384 (int32), bias : V = 4096, W : V*FAN (largest)
// ---------------------------------------------------------------------------
extern "C" void kernel_launch(void* const* d_in, const int* in_sizes, int n_in,
                              void* d_out, int out_size) {
    const int*   idx  = nullptr;
    const float* W    = nullptr;
    const float* bias = nullptr;

    for (int i = 0; i < n_in; i++) {
        if (in_sizes[i] == NPOS)      idx  = (const int*)d_in[i];
        else if (in_sizes[i] == VV)   bias = (const float*)d_in[i];
        else                          W    = (const float*)d_in[i];
    }

    dim3 tblock(8, 32);
    dim3 tgrid(CMAIN / CT, VV / 32);          // (128, 128), y outer
    ngram_transpose_main<<<tgrid, tblock>>>(W);
    ngram_transpose_rem<<<64, 256>>>(W);      // 4 rows * 4096 = 16384 threads

    dim3 ggrid(NPOS / 8, NCH);                // (2048, 4)
    ngram_gather_kernel<<<ggrid, 256>>>(idx, bias, (float*)d_out);
}